// round 1
// baseline (speedup 1.0000x reference)
#include <cuda_runtime.h>
#include <math_constants.h>

#define BB 2
#define SS 2048
#define DD 1024
#define HH 16
#define DHH 64
#define SCALE 0.125f  // DH^-0.5 = 64^-0.5

// ---------------- scratch (no allocations allowed) ----------------
__device__ float g_q[BB * SS * DD];
__device__ float g_k[BB * SS * DD];
__device__ float g_v[BB * SS * DD];
__device__ float g_ctx[BB * SS * DD];
// fallback if attn is not part of d_out (512 MB, bss)
__device__ float g_attn[(long long)BB * HH * SS * SS];

// ---------------- generic NT GEMM ----------------
// C[m,n] = alpha * sum_k A[m*lda + k] * B[n*ldbn + k*ldbk]  (+ bias[n])
// batched over z: z1 = z / Z2, z2 = z % Z2, base += z1*S1 + z2*S2
constexpr int BM = 64, BN = 64, BK = 16;

template <bool BKCONTIG>
__global__ __launch_bounds__(256) void gemm_nt(
    const float* __restrict__ A, const float* __restrict__ Bm,
    const float* __restrict__ bias, float* __restrict__ C,
    int M, int N, int K,
    int lda, int ldbn, int ldbk, int ldc,
    long long aS1, long long aS2,
    long long bS1, long long bS2,
    long long cS1, long long cS2, int Z2,
    float alpha)
{
    int z = blockIdx.z;
    int z1 = z / Z2, z2 = z % Z2;
    A += z1 * aS1 + z2 * aS2;
    Bm += z1 * bS1 + z2 * bS2;
    C += z1 * cS1 + z2 * cS2;

    __shared__ float As[BK][BM + 1];
    __shared__ float Bs[BK][BN + 1];

    int tid = threadIdx.x;
    int tx = tid % 16, ty = tid / 16;
    int m0 = blockIdx.y * BM, n0 = blockIdx.x * BN;

    float acc[4][4] = {};

    for (int k0 = 0; k0 < K; k0 += BK) {
        // load A tile: 64x16, k contiguous in gmem
        #pragma unroll
        for (int i = 0; i < 4; i++) {
            int idx = tid + i * 256;
            int kk = idx % BK, mm = idx / BK;
            As[kk][mm] = A[(long long)(m0 + mm) * lda + (k0 + kk)];
        }
        // load B tile: 64(n) x 16(k)
        #pragma unroll
        for (int i = 0; i < 4; i++) {
            int idx = tid + i * 256;
            int kk, nn;
            if (BKCONTIG) { kk = idx % BK; nn = idx / BK; }
            else          { nn = idx % BN; kk = idx / BN; }
            Bs[kk][nn] = Bm[(long long)(n0 + nn) * ldbn +
                            (long long)(k0 + kk) * ldbk];
        }
        __syncthreads();

        #pragma unroll
        for (int kk = 0; kk < BK; kk++) {
            float a[4], b[4];
            #pragma unroll
            for (int i = 0; i < 4; i++) a[i] = As[kk][ty * 4 + i];
            #pragma unroll
            for (int j = 0; j < 4; j++) b[j] = Bs[kk][tx * 4 + j];
            #pragma unroll
            for (int i = 0; i < 4; i++)
                #pragma unroll
                for (int j = 0; j < 4; j++)
                    acc[i][j] += a[i] * b[j];
        }
        __syncthreads();
    }

    #pragma unroll
    for (int i = 0; i < 4; i++) {
        int m = m0 + ty * 4 + i;
        #pragma unroll
        for (int j = 0; j < 4; j++) {
            int n = n0 + tx * 4 + j;
            float v = acc[i][j] * alpha;
            if (bias) v += bias[n];
            C[(long long)m * ldc + n] = v;
        }
    }
}

// ---------------- row softmax (in place), with mask ----------------
// one block per row of attn [B*H*S rows, S cols]; mask[b,q,k]
__global__ __launch_bounds__(256) void softmax_rows(
    float* __restrict__ attn, const int* __restrict__ mask)
{
    long long r = blockIdx.x;  // 0 .. B*H*S-1
    int q = (int)(r % SS);
    int b = (int)(r / ((long long)HH * SS));
    float* row = attn + r * (long long)SS;
    const int* mrow = mask + ((long long)b * SS + q) * SS;

    int tid = threadIdx.x;
    float vals[8];
    float mx = -CUDART_INF_F;
    #pragma unroll
    for (int i = 0; i < 8; i++) {
        int c = tid + i * 256;
        float v = row[c];
        if (mrow[c] == 0) v = -1e9f;
        vals[i] = v;
        mx = fmaxf(mx, v);
    }

    __shared__ float red[32];
    // warp reduce max
    #pragma unroll
    for (int o = 16; o > 0; o >>= 1)
        mx = fmaxf(mx, __shfl_xor_sync(0xFFFFFFFF, mx, o));
    if ((tid & 31) == 0) red[tid >> 5] = mx;
    __syncthreads();
    if (tid < 32) {
        float v = (tid < 8) ? red[tid] : -CUDART_INF_F;
        #pragma unroll
        for (int o = 4; o > 0; o >>= 1)
            v = fmaxf(v, __shfl_xor_sync(0xFFFFFFFF, v, o));
        if (tid == 0) red[0] = v;
    }
    __syncthreads();
    mx = red[0];
    __syncthreads();

    float sum = 0.f;
    #pragma unroll
    for (int i = 0; i < 8; i++) {
        vals[i] = __expf(vals[i] - mx);
        sum += vals[i];
    }
    // warp reduce sum
    #pragma unroll
    for (int o = 16; o > 0; o >>= 1)
        sum += __shfl_xor_sync(0xFFFFFFFF, sum, o);
    if ((tid & 31) == 0) red[tid >> 5] = sum;
    __syncthreads();
    if (tid < 32) {
        float v = (tid < 8) ? red[tid] : 0.f;
        #pragma unroll
        for (int o = 4; o > 0; o >>= 1)
            v += __shfl_xor_sync(0xFFFFFFFF, v, o);
        if (tid == 0) red[0] = v;
    }
    __syncthreads();
    float inv = 1.f / red[0];

    #pragma unroll
    for (int i = 0; i < 8; i++) {
        int c = tid + i * 256;
        row[c] = vals[i] * inv;
    }
}

// ---------------- launch ----------------
extern "C" void kernel_launch(void* const* d_in, const int* in_sizes, int n_in,
                              void* d_out, int out_size)
{
    const float* x    = (const float*)d_in[0];
    const int*   mask = (const int*)  d_in[1];
    const float* wq_w = (const float*)d_in[2];
    const float* wq_b = (const float*)d_in[3];
    const float* wk_w = (const float*)d_in[4];
    const float* wk_b = (const float*)d_in[5];
    const float* wv_w = (const float*)d_in[6];
    const float* wv_b = (const float*)d_in[7];
    const float* wo_w = (const float*)d_in[8];
    const float* wo_b = (const float*)d_in[9];

    float* out = (float*)d_out;

    const long long OUT_ELEMS  = (long long)BB * SS * DD;          //   4,194,304
    const long long ATTN_ELEMS = (long long)BB * HH * SS * SS;     // 134,217,728

    float *q, *k, *v, *ctx, *attn;
    cudaGetSymbolAddress((void**)&q,   g_q);
    cudaGetSymbolAddress((void**)&k,   g_k);
    cudaGetSymbolAddress((void**)&v,   g_v);
    cudaGetSymbolAddress((void**)&ctx, g_ctx);
    if ((long long)out_size >= OUT_ELEMS + ATTN_ELEMS) {
        attn = out + OUT_ELEMS;   // harness wants (out, attn) concatenated
    } else {
        cudaGetSymbolAddress((void**)&attn, g_attn);
    }

    const int M = BB * SS;  // 4096

    // 1) Q/K/V projections: [4096,1024] @ W^T[1024,1024] + b
    {
        dim3 grid(DD / BN, M / BM, 1);
        gemm_nt<true><<<grid, 256>>>(x, wq_w, wq_b, q, M, DD, DD,
                                     DD, DD, 1, DD,
                                     0, 0, 0, 0, 0, 0, 1, 1.0f);
        gemm_nt<true><<<grid, 256>>>(x, wk_w, wk_b, k, M, DD, DD,
                                     DD, DD, 1, DD,
                                     0, 0, 0, 0, 0, 0, 1, 1.0f);
        gemm_nt<true><<<grid, 256>>>(x, wv_w, wv_b, v, M, DD, DD,
                                     DD, DD, 1, DD,
                                     0, 0, 0, 0, 0, 0, 1, 1.0f);
    }

    // 2) scores[b,h] = SCALE * Q_h @ K_h^T  -> written straight into attn buffer
    {
        dim3 grid(SS / BN, SS / BM, BB * HH);
        gemm_nt<true><<<grid, 256>>>(
            q, k, nullptr, attn, SS, SS, DHH,
            DD, DD, 1, SS,
            (long long)SS * DD, DHH,           // A strides (per b, per h)
            (long long)SS * DD, DHH,           // B strides
            (long long)HH * SS * SS, (long long)SS * SS,  // C strides
            HH, SCALE);
    }

    // 3) softmax rows in place (mask applied)
    {
        softmax_rows<<<(unsigned)((long long)BB * HH * SS), 256>>>(attn, mask);
    }

    // 4) ctx[b,q,h,:] = attn[b,h,q,:] @ V_h   (B operand strided over k)
    {
        dim3 grid(DHH / BN, SS / BM, BB * HH);
        gemm_nt<false><<<grid, 256>>>(
            attn, v, nullptr, ctx, SS, DHH, SS,
            SS, 1, DD, DD,
            (long long)HH * SS * SS, (long long)SS * SS,
            (long long)SS * DD, DHH,
            (long long)SS * DD, DHH,
            HH, 1.0f);
    }

    // 5) out = ctx @ wo^T + wo_b
    {
        dim3 grid(DD / BN, M / BM, 1);
        gemm_nt<true><<<grid, 256>>>(ctx, wo_w, wo_b, out, M, DD, DD,
                                     DD, DD, 1, DD,
                                     0, 0, 0, 0, 0, 0, 1, 1.0f);
    }
}

// round 5
// speedup vs baseline: 1.6550x; 1.6550x over previous
#include <cuda_runtime.h>
#include <math_constants.h>

#define BB 2
#define SS 2048
#define DD 1024
#define HH 16
#define DHH 64
#define SCALE 0.125f  // DH^-0.5

// ---------------- scratch (no allocations allowed) ----------------
__device__ float g_q[BB * SS * DD];
__device__ float g_k[BB * SS * DD];
__device__ float g_v[BB * SS * DD];
__device__ float g_ctx[BB * SS * DD];
__device__ float g_attn[(long long)BB * HH * SS * SS];  // fallback if attn not exported

// =================================================================
// Tiled GEMM: C[m,n] = alpha * sum_k A[m,k]*B(n,k) (+bias[n])
//   TBM=128, TBK=16, 256 threads, microtile 8 x TN.
//   BNC=false: B is [n, k] with k contiguous (ldbn row stride)  -> transpose-scatter
//   BNC=true : B is [k, n] with n contiguous (ldbk row stride)  -> direct float4
//   batched over z: z1=z/Z2, z2=z%Z2
// =================================================================
template <int TBN, int TN, bool BNC>
__global__ __launch_bounds__(256) void gemm128(
    const float* __restrict__ A, const float* __restrict__ Bm,
    const float* __restrict__ bias, float* __restrict__ C,
    int K, int lda, int ldbn, int ldbk, int ldc,
    long long aS1, long long aS2,
    long long bS1, long long bS2,
    long long cS1, long long cS2, int Z2,
    float alpha)
{
    constexpr int TBM = 128, TBK = 16;
    int z = blockIdx.z;
    int z1 = z / Z2, z2 = z % Z2;
    A  += z1 * aS1 + z2 * aS2;
    Bm += z1 * bS1 + z2 * bS2;
    C  += z1 * cS1 + z2 * cS2;

    __shared__ float As[TBK][TBM + 4];
    __shared__ float Bs[TBK][TBN + 4];

    int tid = threadIdx.x;
    int tx = tid % 16, ty = tid / 16;   // 16x16 thread grid
    int m0 = blockIdx.y * TBM, n0 = blockIdx.x * TBN;

    float acc[8][TN] = {};

    for (int k0 = 0; k0 < K; k0 += TBK) {
        // ---- load A tile (128 x 16), k contiguous: float4 + scatter ----
        #pragma unroll
        for (int i = 0; i < 2; i++) {
            int idx = tid + i * 256;          // 512 float4 total
            int row = idx >> 2, kq = idx & 3;
            float4 v = *(const float4*)&A[(long long)(m0 + row) * lda + k0 + kq * 4];
            As[kq * 4 + 0][row] = v.x;
            As[kq * 4 + 1][row] = v.y;
            As[kq * 4 + 2][row] = v.z;
            As[kq * 4 + 3][row] = v.w;
        }
        // ---- load B tile ----
        if (BNC) {
            // B[k, n], n contiguous: direct vector copy
            constexpr int NF4 = TBK * TBN / 4 / 256;  // float4 per thread
            #pragma unroll
            for (int i = 0; i < NF4; i++) {
                int idx = tid + i * 256;
                int kk = idx / (TBN / 4), nq = idx % (TBN / 4);
                float4 v = *(const float4*)&Bm[(long long)(k0 + kk) * ldbk + n0 + nq * 4];
                *(float4*)&Bs[kk][nq * 4] = v;
            }
        } else {
            // B[n, k], k contiguous: float4 + scatter
            constexpr int NF4 = TBN * TBK / 4 / 256;
            #pragma unroll
            for (int i = 0; i < NF4; i++) {
                int idx = tid + i * 256;
                int row = idx >> 2, kq = idx & 3;
                float4 v = *(const float4*)&Bm[(long long)(n0 + row) * ldbn + k0 + kq * 4];
                Bs[kq * 4 + 0][row] = v.x;
                Bs[kq * 4 + 1][row] = v.y;
                Bs[kq * 4 + 2][row] = v.z;
                Bs[kq * 4 + 3][row] = v.w;
            }
        }
        __syncthreads();

        #pragma unroll
        for (int kk = 0; kk < TBK; kk++) {
            float a[8], b[TN];
            *(float4*)&a[0] = *(const float4*)&As[kk][ty * 4];
            *(float4*)&a[4] = *(const float4*)&As[kk][64 + ty * 4];
            *(float4*)&b[0] = *(const float4*)&Bs[kk][tx * 4];
            if (TN == 8)
                *(float4*)&b[4] = *(const float4*)&Bs[kk][64 + tx * 4];
            #pragma unroll
            for (int i = 0; i < 8; i++)
                #pragma unroll
                for (int j = 0; j < TN; j++)
                    acc[i][j] += a[i] * b[j];
        }
        __syncthreads();
    }

    // ---- writeback (float4 stores) ----
    #pragma unroll
    for (int h2 = 0; h2 < 2; h2++) {
        #pragma unroll
        for (int i = 0; i < 4; i++) {
            int m = m0 + h2 * 64 + ty * 4 + i;
            int ai = h2 * 4 + i;
            #pragma unroll
            for (int g = 0; g < TN / 4; g++) {
                int n = n0 + g * 64 + tx * 4;
                float4 v;
                v.x = acc[ai][g * 4 + 0] * alpha;
                v.y = acc[ai][g * 4 + 1] * alpha;
                v.z = acc[ai][g * 4 + 2] * alpha;
                v.w = acc[ai][g * 4 + 3] * alpha;
                if (bias) {
                    float4 bv = *(const float4*)&bias[n];
                    v.x += bv.x; v.y += bv.y; v.z += bv.z; v.w += bv.w;
                }
                *(float4*)&C[(long long)m * ldc + n] = v;
            }
        }
    }
}

// ---------------- row softmax (in place), float4, with mask ----------------
__global__ __launch_bounds__(256) void softmax_rows(
    float* __restrict__ attn, const int* __restrict__ mask)
{
    long long r = blockIdx.x;  // 0 .. B*H*S-1
    int q = (int)(r % SS);
    int b = (int)(r / ((long long)HH * SS));
    float* row = attn + r * (long long)SS;
    const int* mrow = mask + ((long long)b * SS + q) * SS;

    int tid = threadIdx.x;
    float4 vals[2];
    float mx = -CUDART_INF_F;
    #pragma unroll
    for (int i = 0; i < 2; i++) {
        int c = (tid + i * 256) * 4;
        float4 v = *(const float4*)&row[c];
        int4 mv = *(const int4*)&mrow[c];
        if (mv.x == 0) v.x = -1e9f;
        if (mv.y == 0) v.y = -1e9f;
        if (mv.z == 0) v.z = -1e9f;
        if (mv.w == 0) v.w = -1e9f;
        vals[i] = v;
        mx = fmaxf(mx, fmaxf(fmaxf(v.x, v.y), fmaxf(v.z, v.w)));
    }

    __shared__ float red[32];
    #pragma unroll
    for (int o = 16; o > 0; o >>= 1)
        mx = fmaxf(mx, __shfl_xor_sync(0xFFFFFFFF, mx, o));
    if ((tid & 31) == 0) red[tid >> 5] = mx;
    __syncthreads();
    if (tid < 32) {
        float v = (tid < 8) ? red[tid] : -CUDART_INF_F;
        #pragma unroll
        for (int o = 4; o > 0; o >>= 1)
            v = fmaxf(v, __shfl_xor_sync(0xFFFFFFFF, v, o));
        if (tid == 0) red[0] = v;
    }
    __syncthreads();
    mx = red[0];
    __syncthreads();

    float sum = 0.f;
    #pragma unroll
    for (int i = 0; i < 2; i++) {
        vals[i].x = __expf(vals[i].x - mx);
        vals[i].y = __expf(vals[i].y - mx);
        vals[i].z = __expf(vals[i].z - mx);
        vals[i].w = __expf(vals[i].w - mx);
        sum += vals[i].x + vals[i].y + vals[i].z + vals[i].w;
    }
    #pragma unroll
    for (int o = 16; o > 0; o >>= 1)
        sum += __shfl_xor_sync(0xFFFFFFFF, sum, o);
    if ((tid & 31) == 0) red[tid >> 5] = sum;
    __syncthreads();
    if (tid < 32) {
        float v = (tid < 8) ? red[tid] : 0.f;
        #pragma unroll
        for (int o = 4; o > 0; o >>= 1)
            v += __shfl_xor_sync(0xFFFFFFFF, v, o);
        if (tid == 0) red[0] = v;
    }
    __syncthreads();
    float inv = 1.f / red[0];

    #pragma unroll
    for (int i = 0; i < 2; i++) {
        int c = (tid + i * 256) * 4;
        float4 v = vals[i];
        v.x *= inv; v.y *= inv; v.z *= inv; v.w *= inv;
        *(float4*)&row[c] = v;
    }
}

// ---------------- launch ----------------
extern "C" void kernel_launch(void* const* d_in, const int* in_sizes, int n_in,
                              void* d_out, int out_size)
{
    const float* x    = (const float*)d_in[0];
    const int*   mask = (const int*)  d_in[1];
    const float* wq_w = (const float*)d_in[2];
    const float* wq_b = (const float*)d_in[3];
    const float* wk_w = (const float*)d_in[4];
    const float* wk_b = (const float*)d_in[5];
    const float* wv_w = (const float*)d_in[6];
    const float* wv_b = (const float*)d_in[7];
    const float* wo_w = (const float*)d_in[8];
    const float* wo_b = (const float*)d_in[9];

    float* out = (float*)d_out;

    const long long OUT_ELEMS  = (long long)BB * SS * DD;
    const long long ATTN_ELEMS = (long long)BB * HH * SS * SS;

    float *q, *k, *v, *ctx, *attn;
    cudaGetSymbolAddress((void**)&q,   g_q);
    cudaGetSymbolAddress((void**)&k,   g_k);
    cudaGetSymbolAddress((void**)&v,   g_v);
    cudaGetSymbolAddress((void**)&ctx, g_ctx);
    if ((long long)out_size >= OUT_ELEMS + ATTN_ELEMS) {
        attn = out + OUT_ELEMS;
    } else {
        cudaGetSymbolAddress((void**)&attn, g_attn);
    }

    const int M = BB * SS;  // 4096

    // 1) Q/K/V projections: [4096,1024] @ W^T + b
    {
        dim3 grid(DD / 128, M / 128, 1);
        gemm128<128, 8, false><<<grid, 256>>>(x, wq_w, wq_b, q, DD,
            DD, DD, 0, DD, 0, 0, 0, 0, 0, 0, 1, 1.0f);
        gemm128<128, 8, false><<<grid, 256>>>(x, wk_w, wk_b, k, DD,
            DD, DD, 0, DD, 0, 0, 0, 0, 0, 0, 1, 1.0f);
        gemm128<128, 8, false><<<grid, 256>>>(x, wv_w, wv_b, v, DD,
            DD, DD, 0, DD, 0, 0, 0, 0, 0, 0, 1, 1.0f);
    }

    // 2) scores[b,h] = SCALE * Q_h @ K_h^T  (into attn buffer)
    {
        dim3 grid(SS / 128, SS / 128, BB * HH);
        gemm128<128, 8, false><<<grid, 256>>>(
            q, k, nullptr, attn, DHH,
            DD, DD, 0, SS,
            (long long)SS * DD, DHH,
            (long long)SS * DD, DHH,
            (long long)HH * SS * SS, (long long)SS * SS,
            HH, SCALE);
    }

    // 3) softmax rows in place
    softmax_rows<<<(unsigned)((long long)BB * HH * SS), 256>>>(attn, mask);

    // 4) ctx[b,q,h,:] = attn[b,h,q,:] @ V_h  (B is [k,n], n contiguous)
    {
        dim3 grid(DHH / 64, SS / 128, BB * HH);
        gemm128<64, 4, true><<<grid, 256>>>(
            attn, v, nullptr, ctx, SS,
            SS, 0, DD, DD,
            (long long)HH * SS * SS, (long long)SS * SS,
            (long long)SS * DD, DHH,
            (long long)SS * DD, DHH,
            HH, 1.0f);
    }

    // 5) out = ctx @ wo^T + wo_b
    {
        dim3 grid(DD / 128, M / 128, 1);
        gemm128<128, 8, false><<<grid, 256>>>(ctx, wo_w, wo_b, out, DD,
            DD, DD, 0, DD, 0, 0, 0, 0, 0, 0, 1, 1.0f);
    }
}

// round 10
// speedup vs baseline: 2.4874x; 1.5030x over previous
#include <cuda_runtime.h>
#include <math_constants.h>
#include <stdint.h>

#define BB 2
#define SS 2048
#define DD 1024
#define HH 16
#define DHH 64
#define SCALE 0.125f  // DH^-0.5

// ---------------- scratch (no allocations allowed) ----------------
__device__ float g_q[BB * SS * DD];
__device__ float g_k[BB * SS * DD];
__device__ float g_v[BB * SS * DD];
__device__ float g_ctx[BB * SS * DD];
__device__ float g_attn[(long long)BB * HH * SS * SS];  // fallback if attn not exported

// ---------------- tf32 helpers ----------------
__device__ __forceinline__ float f2tf(float x) {
    uint32_t u;
    asm("cvt.rna.tf32.f32 %0, %1;" : "=r"(u) : "f"(x));
    return __uint_as_float(u);
}

__device__ __forceinline__ void mma8(float* c, const uint32_t* a, const uint32_t* b) {
    asm volatile(
        "mma.sync.aligned.m16n8k8.row.col.f32.tf32.tf32.f32 "
        "{%0,%1,%2,%3}, {%4,%5,%6,%7}, {%8,%9}, {%0,%1,%2,%3};\n"
        : "+f"(c[0]), "+f"(c[1]), "+f"(c[2]), "+f"(c[3])
        : "r"(a[0]), "r"(a[1]), "r"(a[2]), "r"(a[3]),
          "r"(b[0]), "r"(b[1]));
}

// =================================================================
// TF32 tensor-core GEMM: C[m,n] = alpha*sum_k A[m,k]*B(n,k) (+bias)
//   256 threads; block tile BM x BN, k-tile BK=32.
//   warp tile WM x WN; warps laid out (BM/WM) x (BN/WN), m-fastest.
//   BNC=false: B is [n,k], k contiguous (weights, K matrix)
//   BNC=true : B is [k,n], n contiguous (V matrix)
//   batched over z: z1=z/Z2, z2=z%Z2
// =================================================================
template <int BM, int BN, int BK, int WM, int WN, bool BNC>
__global__ __launch_bounds__(256, 2) void gemm_tf32(
    const float* __restrict__ A, const float* __restrict__ Bm,
    const float* __restrict__ bias, float* __restrict__ C,
    int K, int lda, int ldbn, int ldbk, int ldc,
    long long aS1, long long aS2,
    long long bS1, long long bS2,
    long long cS1, long long cS2, int Z2,
    float alpha)
{
    constexpr int WARPS_M = BM / WM;
    constexpr int MT = WM / 16;     // mma tiles along m per warp
    constexpr int NT = WN / 8;      // mma tiles along n per warp

    int z = blockIdx.z;
    int z1 = z / Z2, z2 = z % Z2;
    A  += z1 * aS1 + z2 * aS2;
    Bm += z1 * bS1 + z2 * bS2;
    C  += z1 * cS1 + z2 * cS2;

    __shared__ float As[BK][BM + 8];
    __shared__ float Bs[BK][BN + 8];

    int tid  = threadIdx.x;
    int lane = tid & 31, warp = tid >> 5;
    int gid = lane >> 2, tig = lane & 3;
    int warp_m = (warp % WARPS_M) * WM;
    int warp_n = (warp / WARPS_M) * WN;
    int m0 = blockIdx.y * BM, n0 = blockIdx.x * BN;

    float acc[MT][NT][4] = {};

    for (int k0 = 0; k0 < K; k0 += BK) {
        // ---- A tile (BM x BK), k contiguous: float4 load + tf32 + scatter ----
        #pragma unroll
        for (int i = 0; i < BM * BK / (4 * 256); i++) {
            int idx = tid + i * 256;
            int row = idx >> 3, kq = idx & 7;   // 8 float4 per row (BK=32)
            float4 v = *(const float4*)&A[(long long)(m0 + row) * lda + k0 + kq * 4];
            As[kq * 4 + 0][row] = f2tf(v.x);
            As[kq * 4 + 1][row] = f2tf(v.y);
            As[kq * 4 + 2][row] = f2tf(v.z);
            As[kq * 4 + 3][row] = f2tf(v.w);
        }
        // ---- B tile -> Bs[k][n] ----
        if (BNC) {
            #pragma unroll
            for (int i = 0; i < BK * BN / (4 * 256); i++) {
                int idx = tid + i * 256;
                int kk = idx / (BN / 4), nq = idx % (BN / 4);
                float4 v = *(const float4*)&Bm[(long long)(k0 + kk) * ldbk + n0 + nq * 4];
                float4 w;
                w.x = f2tf(v.x); w.y = f2tf(v.y); w.z = f2tf(v.z); w.w = f2tf(v.w);
                *(float4*)&Bs[kk][nq * 4] = w;
            }
        } else {
            #pragma unroll
            for (int i = 0; i < BN * BK / (4 * 256); i++) {
                int idx = tid + i * 256;
                int row = idx >> 3, kq = idx & 7;
                float4 v = *(const float4*)&Bm[(long long)(n0 + row) * ldbn + k0 + kq * 4];
                Bs[kq * 4 + 0][row] = f2tf(v.x);
                Bs[kq * 4 + 1][row] = f2tf(v.y);
                Bs[kq * 4 + 2][row] = f2tf(v.z);
                Bs[kq * 4 + 3][row] = f2tf(v.w);
            }
        }
        __syncthreads();

        #pragma unroll
        for (int ks = 0; ks < BK; ks += 8) {
            uint32_t af[MT][4], bf[NT][2];
            #pragma unroll
            for (int i = 0; i < MT; i++) {
                int mb = warp_m + i * 16 + gid;
                af[i][0] = __float_as_uint(As[ks + tig    ][mb]);
                af[i][1] = __float_as_uint(As[ks + tig    ][mb + 8]);
                af[i][2] = __float_as_uint(As[ks + tig + 4][mb]);
                af[i][3] = __float_as_uint(As[ks + tig + 4][mb + 8]);
            }
            #pragma unroll
            for (int j = 0; j < NT; j++) {
                int nb = warp_n + j * 8 + gid;
                bf[j][0] = __float_as_uint(Bs[ks + tig    ][nb]);
                bf[j][1] = __float_as_uint(Bs[ks + tig + 4][nb]);
            }
            #pragma unroll
            for (int i = 0; i < MT; i++)
                #pragma unroll
                for (int j = 0; j < NT; j++)
                    mma8(acc[i][j], af[i], bf[j]);
        }
        __syncthreads();
    }

    // ---- epilogue: float2 stores ----
    #pragma unroll
    for (int i = 0; i < MT; i++) {
        int r0 = m0 + warp_m + i * 16 + gid;
        #pragma unroll
        for (int j = 0; j < NT; j++) {
            int c0 = n0 + warp_n + j * 8 + tig * 2;
            float2 bv = make_float2(0.f, 0.f);
            if (bias) bv = *(const float2*)&bias[c0];
            float2 v0, v1;
            v0.x = acc[i][j][0] * alpha + bv.x;
            v0.y = acc[i][j][1] * alpha + bv.y;
            v1.x = acc[i][j][2] * alpha + bv.x;
            v1.y = acc[i][j][3] * alpha + bv.y;
            *(float2*)&C[(long long)r0 * ldc + c0]       = v0;
            *(float2*)&C[(long long)(r0 + 8) * ldc + c0] = v1;
        }
    }
}

// ---------------- row softmax (in place), float4, with mask ----------------
__global__ __launch_bounds__(256) void softmax_rows(
    float* __restrict__ attn, const int* __restrict__ mask)
{
    long long r = blockIdx.x;  // 0 .. B*H*S-1
    int q = (int)(r % SS);
    int b = (int)(r / ((long long)HH * SS));
    float* row = attn + r * (long long)SS;
    const int* mrow = mask + ((long long)b * SS + q) * SS;

    int tid = threadIdx.x;
    float4 vals[2];
    float mx = -CUDART_INF_F;
    #pragma unroll
    for (int i = 0; i < 2; i++) {
        int c = (tid + i * 256) * 4;
        float4 v = *(const float4*)&row[c];
        int4 mv = *(const int4*)&mrow[c];
        if (mv.x == 0) v.x = -1e9f;
        if (mv.y == 0) v.y = -1e9f;
        if (mv.z == 0) v.z = -1e9f;
        if (mv.w == 0) v.w = -1e9f;
        vals[i] = v;
        mx = fmaxf(mx, fmaxf(fmaxf(v.x, v.y), fmaxf(v.z, v.w)));
    }

    __shared__ float red[32];
    #pragma unroll
    for (int o = 16; o > 0; o >>= 1)
        mx = fmaxf(mx, __shfl_xor_sync(0xFFFFFFFF, mx, o));
    if ((tid & 31) == 0) red[tid >> 5] = mx;
    __syncthreads();
    if (tid < 32) {
        float v = (tid < 8) ? red[tid] : -CUDART_INF_F;
        #pragma unroll
        for (int o = 4; o > 0; o >>= 1)
            v = fmaxf(v, __shfl_xor_sync(0xFFFFFFFF, v, o));
        if (tid == 0) red[0] = v;
    }
    __syncthreads();
    mx = red[0];
    __syncthreads();

    float sum = 0.f;
    #pragma unroll
    for (int i = 0; i < 2; i++) {
        vals[i].x = __expf(vals[i].x - mx);
        vals[i].y = __expf(vals[i].y - mx);
        vals[i].z = __expf(vals[i].z - mx);
        vals[i].w = __expf(vals[i].w - mx);
        sum += vals[i].x + vals[i].y + vals[i].z + vals[i].w;
    }
    #pragma unroll
    for (int o = 16; o > 0; o >>= 1)
        sum += __shfl_xor_sync(0xFFFFFFFF, sum, o);
    if ((tid & 31) == 0) red[tid >> 5] = sum;
    __syncthreads();
    if (tid < 32) {
        float v = (tid < 8) ? red[tid] : 0.f;
        #pragma unroll
        for (int o = 4; o > 0; o >>= 1)
            v += __shfl_xor_sync(0xFFFFFFFF, v, o);
        if (tid == 0) red[0] = v;
    }
    __syncthreads();
    float inv = 1.f / red[0];

    #pragma unroll
    for (int i = 0; i < 2; i++) {
        int c = (tid + i * 256) * 4;
        float4 v = vals[i];
        v.x *= inv; v.y *= inv; v.z *= inv; v.w *= inv;
        *(float4*)&row[c] = v;
    }
}

// ---------------- launch ----------------
extern "C" void kernel_launch(void* const* d_in, const int* in_sizes, int n_in,
                              void* d_out, int out_size)
{
    const float* x    = (const float*)d_in[0];
    const int*   mask = (const int*)  d_in[1];
    const float* wq_w = (const float*)d_in[2];
    const float* wq_b = (const float*)d_in[3];
    const float* wk_w = (const float*)d_in[4];
    const float* wk_b = (const float*)d_in[5];
    const float* wv_w = (const float*)d_in[6];
    const float* wv_b = (const float*)d_in[7];
    const float* wo_w = (const float*)d_in[8];
    const float* wo_b = (const float*)d_in[9];

    float* out = (float*)d_out;

    const long long OUT_ELEMS  = (long long)BB * SS * DD;
    const long long ATTN_ELEMS = (long long)BB * HH * SS * SS;

    float *q, *k, *v, *ctx, *attn;
    cudaGetSymbolAddress((void**)&q,   g_q);
    cudaGetSymbolAddress((void**)&k,   g_k);
    cudaGetSymbolAddress((void**)&v,   g_v);
    cudaGetSymbolAddress((void**)&ctx, g_ctx);
    if ((long long)out_size >= OUT_ELEMS + ATTN_ELEMS) {
        attn = out + OUT_ELEMS;
    } else {
        cudaGetSymbolAddress((void**)&attn, g_attn);
    }

    const int M = BB * SS;  // 4096

    // 1) Q/K/V projections: [4096,1024] @ W^T + b
    {
        dim3 grid(DD / 128, M / 128, 1);
        gemm_tf32<128, 128, 32, 64, 32, false><<<grid, 256>>>(x, wq_w, wq_b, q, DD,
            DD, DD, 0, DD, 0, 0, 0, 0, 0, 0, 1, 1.0f);
        gemm_tf32<128, 128, 32, 64, 32, false><<<grid, 256>>>(x, wk_w, wk_b, k, DD,
            DD, DD, 0, DD, 0, 0, 0, 0, 0, 0, 1, 1.0f);
        gemm_tf32<128, 128, 32, 64, 32, false><<<grid, 256>>>(x, wv_w, wv_b, v, DD,
            DD, DD, 0, DD, 0, 0, 0, 0, 0, 0, 1, 1.0f);
    }

    // 2) scores[b,h] = SCALE * Q_h @ K_h^T  (into attn buffer)
    {
        dim3 grid(SS / 128, SS / 128, BB * HH);
        gemm_tf32<128, 128, 32, 64, 32, false><<<grid, 256>>>(
            q, k, nullptr, attn, DHH,
            DD, DD, 0, SS,
            (long long)SS * DD, DHH,
            (long long)SS * DD, DHH,
            (long long)HH * SS * SS, (long long)SS * SS,
            HH, SCALE);
    }

    // 3) softmax rows in place
    softmax_rows<<<(unsigned)((long long)BB * HH * SS), 256>>>(attn, mask);

    // 4) ctx[b,q,h,:] = attn[b,h,q,:] @ V_h  (B is [k,n], n contiguous)
    {
        dim3 grid(DHH / 64, SS / 128, BB * HH);
        gemm_tf32<128, 64, 32, 32, 32, true><<<grid, 256>>>(
            attn, v, nullptr, ctx, SS,
            SS, 0, DD, DD,
            (long long)HH * SS * SS, (long long)SS * SS,
            (long long)SS * DD, DHH,
            (long long)SS * DD, DHH,
            HH, 1.0f);
    }

    // 5) out = ctx @ wo^T + wo_b
    {
        dim3 grid(DD / 128, M / 128, 1);
        gemm_tf32<128, 128, 32, 64, 32, false><<<grid, 256>>>(ctx, wo_w, wo_b, out, DD,
            DD, DD, 0, DD, 0, 0, 0, 0, 0, 0, 1, 1.0f);
    }
}

// round 11
// speedup vs baseline: 3.4489x; 1.3865x over previous
#include <cuda_runtime.h>
#include <math_constants.h>
#include <stdint.h>

#define BB 2
#define SS 2048
#define DD 1024
#define HH 16
#define DHH 64
#define SCALE 0.125f  // DH^-0.5

// ---------------- scratch (no allocations allowed) ----------------
__device__ float g_q[BB * SS * DD];
__device__ float g_k[BB * SS * DD];
__device__ float g_v[BB * SS * DD];
__device__ float g_ctx[BB * SS * DD];
__device__ float g_attn[(long long)BB * HH * SS * SS];  // fallback if attn not exported

// ---------------- tf32 helpers ----------------
__device__ __forceinline__ float f2tf(float x) {
    uint32_t u;
    asm("cvt.rna.tf32.f32 %0, %1;" : "=r"(u) : "f"(x));
    return __uint_as_float(u);
}

__device__ __forceinline__ void mma8(float* c, const uint32_t* a, const uint32_t* b) {
    asm volatile(
        "mma.sync.aligned.m16n8k8.row.col.f32.tf32.tf32.f32 "
        "{%0,%1,%2,%3}, {%4,%5,%6,%7}, {%8,%9}, {%0,%1,%2,%3};\n"
        : "+f"(c[0]), "+f"(c[1]), "+f"(c[2]), "+f"(c[3])
        : "r"(a[0]), "r"(a[1]), "r"(a[2]), "r"(a[3]),
          "r"(b[0]), "r"(b[1]));
}

// =================================================================
// TF32 tensor-core GEMM: C[m,n] = alpha*sum_k A[m,k]*B(n,k) (+bias)
//   256 threads; block tile BM x BN, k-tile BK=32.
//   warp tile WM x WN; warps laid out (BM/WM) x (BN/WN), m-fastest.
//   Smem tiles XOR-swizzled: element (k, m) lives at column m ^ (k & 0x1C)
//   -> conflict-free transpose-scatter STS and conflict-free fragment LDS.
//   BNC=false: B is [n,k], k contiguous (weights, K matrix) -> swizzled
//   BNC=true : B is [k,n], n contiguous (V matrix) -> plain float4 layout
//   batched over z: z1=z/Z2, z2=z%Z2
// =================================================================
template <int BM, int BN, int BK, int WM, int WN, bool BNC>
__global__ __launch_bounds__(256, 2) void gemm_tf32(
    const float* __restrict__ A, const float* __restrict__ Bm,
    const float* __restrict__ bias, float* __restrict__ C,
    int K, int lda, int ldbn, int ldbk, int ldc,
    long long aS1, long long aS2,
    long long bS1, long long bS2,
    long long cS1, long long cS2, int Z2,
    float alpha)
{
    constexpr int WARPS_M = BM / WM;
    constexpr int MT = WM / 16;     // mma tiles along m per warp
    constexpr int NT = WN / 8;      // mma tiles along n per warp

    int z = blockIdx.z;
    int z1 = z / Z2, z2 = z % Z2;
    A  += z1 * aS1 + z2 * aS2;
    Bm += z1 * bS1 + z2 * bS2;
    C  += z1 * cS1 + z2 * cS2;

    __shared__ float As[BK][BM + 8];
    __shared__ float Bs[BK][BN + 8];

    int tid  = threadIdx.x;
    int lane = tid & 31, warp = tid >> 5;
    int gid = lane >> 2, tig = lane & 3;
    int warp_m = (warp % WARPS_M) * WM;
    int warp_n = (warp / WARPS_M) * WN;
    int m0 = blockIdx.y * BM, n0 = blockIdx.x * BN;

    float acc[MT][NT][4] = {};

    for (int k0 = 0; k0 < K; k0 += BK) {
        // ---- A tile (BM x BK), k contiguous: float4 load + tf32 + swizzled scatter ----
        #pragma unroll
        for (int i = 0; i < BM * BK / (4 * 256); i++) {
            int idx = tid + i * 256;
            int row = idx >> 3, kq = idx & 7;   // 8 float4 per gmem row (BK=32)
            float4 v = *(const float4*)&A[(long long)(m0 + row) * lda + k0 + kq * 4];
            int col = row ^ (kq << 2);          // swizzle: same col for all 4 k's
            As[kq * 4 + 0][col] = f2tf(v.x);
            As[kq * 4 + 1][col] = f2tf(v.y);
            As[kq * 4 + 2][col] = f2tf(v.z);
            As[kq * 4 + 3][col] = f2tf(v.w);
        }
        // ---- B tile ----
        if (BNC) {
            // B[k, n], n contiguous: direct float4 copy (already conflict-free)
            #pragma unroll
            for (int i = 0; i < BK * BN / (4 * 256); i++) {
                int idx = tid + i * 256;
                int kk = idx / (BN / 4), nq = idx % (BN / 4);
                float4 v = *(const float4*)&Bm[(long long)(k0 + kk) * ldbk + n0 + nq * 4];
                float4 w;
                w.x = f2tf(v.x); w.y = f2tf(v.y); w.z = f2tf(v.z); w.w = f2tf(v.w);
                *(float4*)&Bs[kk][nq * 4] = w;
            }
        } else {
            // B[n, k], k contiguous: swizzled scatter like A
            #pragma unroll
            for (int i = 0; i < BN * BK / (4 * 256); i++) {
                int idx = tid + i * 256;
                int row = idx >> 3, kq = idx & 7;
                float4 v = *(const float4*)&Bm[(long long)(n0 + row) * ldbn + k0 + kq * 4];
                int col = row ^ (kq << 2);
                Bs[kq * 4 + 0][col] = f2tf(v.x);
                Bs[kq * 4 + 1][col] = f2tf(v.y);
                Bs[kq * 4 + 2][col] = f2tf(v.z);
                Bs[kq * 4 + 3][col] = f2tf(v.w);
            }
        }
        __syncthreads();

        #pragma unroll
        for (int ks = 0; ks < BK; ks += 8) {
            int S0 = ks & 0x18;       // swizzle for k rows ks+tig   (bit2 = 0)
            int S1 = S0 | 4;          // swizzle for k rows ks+tig+4 (bit2 = 1)
            uint32_t af[MT][4], bf[NT][2];
            #pragma unroll
            for (int i = 0; i < MT; i++) {
                int mb = warp_m + i * 16 + gid;
                af[i][0] = __float_as_uint(As[ks + tig    ][mb       ^ S0]);
                af[i][1] = __float_as_uint(As[ks + tig    ][(mb + 8) ^ S0]);
                af[i][2] = __float_as_uint(As[ks + tig + 4][mb       ^ S1]);
                af[i][3] = __float_as_uint(As[ks + tig + 4][(mb + 8) ^ S1]);
            }
            #pragma unroll
            for (int j = 0; j < NT; j++) {
                int nb = warp_n + j * 8 + gid;
                if (BNC) {
                    bf[j][0] = __float_as_uint(Bs[ks + tig    ][nb]);
                    bf[j][1] = __float_as_uint(Bs[ks + tig + 4][nb]);
                } else {
                    bf[j][0] = __float_as_uint(Bs[ks + tig    ][nb ^ S0]);
                    bf[j][1] = __float_as_uint(Bs[ks + tig + 4][nb ^ S1]);
                }
            }
            #pragma unroll
            for (int i = 0; i < MT; i++)
                #pragma unroll
                for (int j = 0; j < NT; j++)
                    mma8(acc[i][j], af[i], bf[j]);
        }
        __syncthreads();
    }

    // ---- epilogue: float2 stores ----
    #pragma unroll
    for (int i = 0; i < MT; i++) {
        int r0 = m0 + warp_m + i * 16 + gid;
        #pragma unroll
        for (int j = 0; j < NT; j++) {
            int c0 = n0 + warp_n + j * 8 + tig * 2;
            float2 bv = make_float2(0.f, 0.f);
            if (bias) bv = *(const float2*)&bias[c0];
            float2 v0, v1;
            v0.x = acc[i][j][0] * alpha + bv.x;
            v0.y = acc[i][j][1] * alpha + bv.y;
            v1.x = acc[i][j][2] * alpha + bv.x;
            v1.y = acc[i][j][3] * alpha + bv.y;
            *(float2*)&C[(long long)r0 * ldc + c0]       = v0;
            *(float2*)&C[(long long)(r0 + 8) * ldc + c0] = v1;
        }
    }
}

// ---------------- row softmax (in place), float4, with mask ----------------
__global__ __launch_bounds__(256) void softmax_rows(
    float* __restrict__ attn, const int* __restrict__ mask)
{
    long long r = blockIdx.x;  // 0 .. B*H*S-1
    int q = (int)(r % SS);
    int b = (int)(r / ((long long)HH * SS));
    float* row = attn + r * (long long)SS;
    const int* mrow = mask + ((long long)b * SS + q) * SS;

    int tid = threadIdx.x;
    float4 vals[2];
    float mx = -CUDART_INF_F;
    #pragma unroll
    for (int i = 0; i < 2; i++) {
        int c = (tid + i * 256) * 4;
        float4 v = *(const float4*)&row[c];
        int4 mv = *(const int4*)&mrow[c];
        if (mv.x == 0) v.x = -1e9f;
        if (mv.y == 0) v.y = -1e9f;
        if (mv.z == 0) v.z = -1e9f;
        if (mv.w == 0) v.w = -1e9f;
        vals[i] = v;
        mx = fmaxf(mx, fmaxf(fmaxf(v.x, v.y), fmaxf(v.z, v.w)));
    }

    __shared__ float red[32];
    #pragma unroll
    for (int o = 16; o > 0; o >>= 1)
        mx = fmaxf(mx, __shfl_xor_sync(0xFFFFFFFF, mx, o));
    if ((tid & 31) == 0) red[tid >> 5] = mx;
    __syncthreads();
    if (tid < 32) {
        float v = (tid < 8) ? red[tid] : -CUDART_INF_F;
        #pragma unroll
        for (int o = 4; o > 0; o >>= 1)
            v = fmaxf(v, __shfl_xor_sync(0xFFFFFFFF, v, o));
        if (tid == 0) red[0] = v;
    }
    __syncthreads();
    mx = red[0];
    __syncthreads();

    float sum = 0.f;
    #pragma unroll
    for (int i = 0; i < 2; i++) {
        vals[i].x = __expf(vals[i].x - mx);
        vals[i].y = __expf(vals[i].y - mx);
        vals[i].z = __expf(vals[i].z - mx);
        vals[i].w = __expf(vals[i].w - mx);
        sum += vals[i].x + vals[i].y + vals[i].z + vals[i].w;
    }
    #pragma unroll
    for (int o = 16; o > 0; o >>= 1)
        sum += __shfl_xor_sync(0xFFFFFFFF, sum, o);
    if ((tid & 31) == 0) red[tid >> 5] = sum;
    __syncthreads();
    if (tid < 32) {
        float v = (tid < 8) ? red[tid] : 0.f;
        #pragma unroll
        for (int o = 4; o > 0; o >>= 1)
            v += __shfl_xor_sync(0xFFFFFFFF, v, o);
        if (tid == 0) red[0] = v;
    }
    __syncthreads();
    float inv = 1.f / red[0];

    #pragma unroll
    for (int i = 0; i < 2; i++) {
        int c = (tid + i * 256) * 4;
        float4 v = vals[i];
        v.x *= inv; v.y *= inv; v.z *= inv; v.w *= inv;
        *(float4*)&row[c] = v;
    }
}

// ---------------- launch ----------------
extern "C" void kernel_launch(void* const* d_in, const int* in_sizes, int n_in,
                              void* d_out, int out_size)
{
    const float* x    = (const float*)d_in[0];
    const int*   mask = (const int*)  d_in[1];
    const float* wq_w = (const float*)d_in[2];
    const float* wq_b = (const float*)d_in[3];
    const float* wk_w = (const float*)d_in[4];
    const float* wk_b = (const float*)d_in[5];
    const float* wv_w = (const float*)d_in[6];
    const float* wv_b = (const float*)d_in[7];
    const float* wo_w = (const float*)d_in[8];
    const float* wo_b = (const float*)d_in[9];

    float* out = (float*)d_out;

    const long long OUT_ELEMS  = (long long)BB * SS * DD;
    const long long ATTN_ELEMS = (long long)BB * HH * SS * SS;

    float *q, *k, *v, *ctx, *attn;
    cudaGetSymbolAddress((void**)&q,   g_q);
    cudaGetSymbolAddress((void**)&k,   g_k);
    cudaGetSymbolAddress((void**)&v,   g_v);
    cudaGetSymbolAddress((void**)&ctx, g_ctx);
    if ((long long)out_size >= OUT_ELEMS + ATTN_ELEMS) {
        attn = out + OUT_ELEMS;
    } else {
        cudaGetSymbolAddress((void**)&attn, g_attn);
    }

    const int M = BB * SS;  // 4096

    // 1) Q/K/V projections: [4096,1024] @ W^T + b
    {
        dim3 grid(DD / 128, M / 128, 1);
        gemm_tf32<128, 128, 32, 64, 32, false><<<grid, 256>>>(x, wq_w, wq_b, q, DD,
            DD, DD, 0, DD, 0, 0, 0, 0, 0, 0, 1, 1.0f);
        gemm_tf32<128, 128, 32, 64, 32, false><<<grid, 256>>>(x, wk_w, wk_b, k, DD,
            DD, DD, 0, DD, 0, 0, 0, 0, 0, 0, 1, 1.0f);
        gemm_tf32<128, 128, 32, 64, 32, false><<<grid, 256>>>(x, wv_w, wv_b, v, DD,
            DD, DD, 0, DD, 0, 0, 0, 0, 0, 0, 1, 1.0f);
    }

    // 2) scores[b,h] = SCALE * Q_h @ K_h^T  (into attn buffer)
    {
        dim3 grid(SS / 128, SS / 128, BB * HH);
        gemm_tf32<128, 128, 32, 64, 32, false><<<grid, 256>>>(
            q, k, nullptr, attn, DHH,
            DD, DD, 0, SS,
            (long long)SS * DD, DHH,
            (long long)SS * DD, DHH,
            (long long)HH * SS * SS, (long long)SS * SS,
            HH, SCALE);
    }

    // 3) softmax rows in place
    softmax_rows<<<(unsigned)((long long)BB * HH * SS), 256>>>(attn, mask);

    // 4) ctx[b,q,h,:] = attn[b,h,q,:] @ V_h  (B is [k,n], n contiguous)
    {
        dim3 grid(DHH / 64, SS / 128, BB * HH);
        gemm_tf32<128, 64, 32, 32, 32, true><<<grid, 256>>>(
            attn, v, nullptr, ctx, SS,
            SS, 0, DD, DD,
            (long long)HH * SS * SS, (long long)SS * SS,
            (long long)SS * DD, DHH,
            (long long)SS * DD, DHH,
            HH, 1.0f);
    }

    // 5) out = ctx @ wo^T + wo_b
    {
        dim3 grid(DD / 128, M / 128, 1);
        gemm_tf32<128, 128, 32, 64, 32, false><<<grid, 256>>>(ctx, wo_w, wo_b, out, DD,
            DD, DD, 0, DD, 0, 0, 0, 0, 0, 0, 1, 1.0f);
    }
}

// round 12
// speedup vs baseline: 4.5136x; 1.3087x over previous
#include <cuda_runtime.h>
#include <math_constants.h>
#include <stdint.h>

#define BB 2
#define SS 2048
#define DD 1024
#define HH 16
#define DHH 64
#define SCALE 0.125f  // DH^-0.5

// ---------------- scratch (no allocations allowed) ----------------
__device__ float g_xt[BB * SS * DD];                     // x, tf32-rounded
__device__ float g_w[4 * DD * DD];                       // wq,wk,wv,wo tf32-rounded
__device__ float g_bqk[2 * DD];                          // packed q,k biases
__device__ float g_qk[2 * BB * SS * DD];                 // q then k (rounded)
__device__ float g_vt[BB * DD * SS];                     // v transposed [b*D+n][s] (rounded)
__device__ float g_ctx[BB * SS * DD];                    // context (rounded)
__device__ float g_attn[(long long)BB * HH * SS * SS];   // fallback if attn not exported

// ---------------- tf32 helpers ----------------
__device__ __forceinline__ float f2tf(float x) {
    uint32_t u;
    asm("cvt.rna.tf32.f32 %0, %1;" : "=r"(u) : "f"(x));
    return __uint_as_float(u);
}

__device__ __forceinline__ void mma8(float* c, const uint32_t* a, const uint32_t* b) {
    asm volatile(
        "mma.sync.aligned.m16n8k8.row.col.f32.tf32.tf32.f32 "
        "{%0,%1,%2,%3}, {%4,%5,%6,%7}, {%8,%9}, {%0,%1,%2,%3};\n"
        : "+f"(c[0]), "+f"(c[1]), "+f"(c[2]), "+f"(c[3])
        : "r"(a[0]), "r"(a[1]), "r"(a[2]), "r"(a[3]),
          "r"(b[0]), "r"(b[1]));
}

__device__ __forceinline__ void cpa16(uint32_t s, const void* g) {
    asm volatile("cp.async.cg.shared.global [%0], [%1], 16;" :: "r"(s), "l"(g) : "memory");
}
__device__ __forceinline__ void cp_commit() {
    asm volatile("cp.async.commit_group;" ::: "memory");
}
template <int N>
__device__ __forceinline__ void cp_wait() {
    asm volatile("cp.async.wait_group %0;" :: "n"(N) : "memory");
}

// ---------------- elementwise tf32 rounding ----------------
__global__ void conv_tf32(const float4* __restrict__ src, float4* __restrict__ dst, int n4) {
    int i = blockIdx.x * 256 + threadIdx.x;
    if (i < n4) {
        float4 v = src[i];
        v.x = f2tf(v.x); v.y = f2tf(v.y); v.z = f2tf(v.z); v.w = f2tf(v.w);
        dst[i] = v;
    }
}
__global__ void pack_bias2(const float* __restrict__ a, const float* __restrict__ b,
                           float* __restrict__ dst) {
    int i = blockIdx.x * 256 + threadIdx.x;
    if (i < DD) { dst[i] = a[i]; dst[DD + i] = b[i]; }
}

// =================================================================
// TF32 GEMM, cp.async double-buffered, both operands [rows][k] with
// k contiguous (A: [m][k], B: [n][k]).  C[m,n] = alpha*A.B^T (+bias)
//   smem row = BK=32 floats = 128B, chunk-swizzled: chunk c of row r
//   stored at c ^ (r&7)  -> conflict-free fills and fragment loads.
//   CONVA: round A fragments to tf32 at load (for fp32 attn operand)
//   ROUND_C: round outputs to tf32 at store (producer-side rounding)
//   TRANS_C: scatter-store C transposed into g_vt layout
// =================================================================
template <int BM, int BN, int BK, int WM, int WN, bool CONVA, bool ROUND_C, bool TRANS_C>
__global__ __launch_bounds__(256, 2) void gemm_cp(
    const float* __restrict__ A, const float* __restrict__ Bm,
    const float* __restrict__ bias, float* __restrict__ C,
    int K, int lda, int ldbn, int ldc,
    long long aS1, long long aS2,
    long long bS1, long long bS2,
    long long cS1, long long cS2,
    long long biasS1, int Z2,
    float alpha)
{
    constexpr int WARPS_M = BM / WM;
    constexpr int MT = WM / 16;
    constexpr int NT = WN / 8;
    constexpr int AF = BM * 8 / 256;   // cp.async per thread for A
    constexpr int BF = BN * 8 / 256;

    int z = blockIdx.z;
    int z1 = z / Z2, z2 = z % Z2;
    A  += z1 * aS1 + z2 * aS2;
    Bm += z1 * bS1 + z2 * bS2;
    C  += z1 * cS1 + z2 * cS2;
    const float* biasp = bias ? bias + z1 * biasS1 : nullptr;

    __shared__ float As[2][BM * BK];
    __shared__ float Bs[2][BN * BK];

    int tid  = threadIdx.x;
    int lane = tid & 31, warp = tid >> 5;
    int gid = lane >> 2, tig = lane & 3;
    int warp_m = (warp % WARPS_M) * WM;
    int warp_n = (warp / WARPS_M) * WN;
    int m0 = blockIdx.y * BM, n0 = blockIdx.x * BN;

    // ---- cp.async fill geometry (per-thread constants) ----
    int rbase = tid >> 3;            // first row this thread fills
    int cch   = tid & 7;             // chunk within row
    int scol  = ((cch ^ (rbase & 7)) << 2);  // swizzled float offset in row
    uint32_t sA0 = (uint32_t)__cvta_generic_to_shared(&As[0][0]);
    uint32_t sB0 = (uint32_t)__cvta_generic_to_shared(&Bs[0][0]);
    uint32_t sAoff = (uint32_t)((rbase * BK + scol) * 4);
    uint32_t sBoff = sAoff;

    int kt_total = K / BK;

    auto load_stage = [&](int st, int k0) {
        uint32_t sa = sA0 + st * (BM * BK * 4) + sAoff;
        const float* ga = A + (long long)(m0 + rbase) * lda + k0 + cch * 4;
        #pragma unroll
        for (int i = 0; i < AF; i++)
            cpa16(sa + i * 32 * BK * 4, ga + (long long)i * 32 * lda);
        uint32_t sb = sB0 + st * (BN * BK * 4) + sBoff;
        const float* gb = Bm + (long long)(n0 + rbase) * ldbn + k0 + cch * 4;
        #pragma unroll
        for (int i = 0; i < BF; i++)
            cpa16(sb + i * 32 * BK * 4, gb + (long long)i * 32 * ldbn);
    };

    float acc[MT][NT][4] = {};

    int mb[MT], nb[NT];
    #pragma unroll
    for (int i = 0; i < MT; i++) mb[i] = warp_m + i * 16 + gid;
    #pragma unroll
    for (int j = 0; j < NT; j++) nb[j] = warp_n + j * 8 + gid;

    load_stage(0, 0);
    cp_commit();

    for (int kt = 0; kt < kt_total; kt++) {
        int cur = kt & 1;
        if (kt + 1 < kt_total) {
            load_stage(cur ^ 1, (kt + 1) * BK);
            cp_commit();
            cp_wait<1>();
        } else {
            cp_wait<0>();
        }
        __syncthreads();

        const float* Ac = As[cur];
        const float* Bc = Bs[cur];
        #pragma unroll
        for (int ks = 0; ks < BK; ks += 8) {
            int c0 = ks >> 2;
            int s0 = ((c0 ^ gid) << 2) + tig;
            int s1 = (((c0 + 1) ^ gid) << 2) + tig;
            uint32_t af[MT][4], bf[NT][2];
            #pragma unroll
            for (int i = 0; i < MT; i++) {
                float a0 = Ac[mb[i] * BK + s0];
                float a1 = Ac[(mb[i] + 8) * BK + s0];
                float a2 = Ac[mb[i] * BK + s1];
                float a3 = Ac[(mb[i] + 8) * BK + s1];
                if (CONVA) { a0 = f2tf(a0); a1 = f2tf(a1); a2 = f2tf(a2); a3 = f2tf(a3); }
                af[i][0] = __float_as_uint(a0);
                af[i][1] = __float_as_uint(a1);
                af[i][2] = __float_as_uint(a2);
                af[i][3] = __float_as_uint(a3);
            }
            #pragma unroll
            for (int j = 0; j < NT; j++) {
                bf[j][0] = __float_as_uint(Bc[nb[j] * BK + s0]);
                bf[j][1] = __float_as_uint(Bc[nb[j] * BK + s1]);
            }
            #pragma unroll
            for (int i = 0; i < MT; i++)
                #pragma unroll
                for (int j = 0; j < NT; j++)
                    mma8(acc[i][j], af[i], bf[j]);
        }
        __syncthreads();
    }

    // ---- epilogue ----
    #pragma unroll
    for (int i = 0; i < MT; i++) {
        int r0 = m0 + warp_m + i * 16 + gid;
        #pragma unroll
        for (int j = 0; j < NT; j++) {
            int c0 = n0 + warp_n + j * 8 + tig * 2;
            float2 bv = make_float2(0.f, 0.f);
            if (biasp) bv = *(const float2*)&biasp[c0];
            float v00 = acc[i][j][0] * alpha + bv.x;
            float v01 = acc[i][j][1] * alpha + bv.y;
            float v10 = acc[i][j][2] * alpha + bv.x;
            float v11 = acc[i][j][3] * alpha + bv.y;
            if (ROUND_C) {
                v00 = f2tf(v00); v01 = f2tf(v01); v10 = f2tf(v10); v11 = f2tf(v11);
            }
            if (TRANS_C) {
                // dst[(b*DD + n)*SS + s],  b = m>>11, s = m&2047
                int b0 = r0 >> 11, s0r = r0 & (SS - 1);
                int b1 = (r0 + 8) >> 11, s1r = (r0 + 8) & (SS - 1);
                C[((long long)(b0 * DD + c0)) * SS + s0r]     = v00;
                C[((long long)(b0 * DD + c0 + 1)) * SS + s0r] = v01;
                C[((long long)(b1 * DD + c0)) * SS + s1r]     = v10;
                C[((long long)(b1 * DD + c0 + 1)) * SS + s1r] = v11;
            } else {
                *(float2*)&C[(long long)r0 * ldc + c0]       = make_float2(v00, v01);
                *(float2*)&C[(long long)(r0 + 8) * ldc + c0] = make_float2(v10, v11);
            }
        }
    }
}

// ---------------- row softmax (in place), float4, with mask ----------------
__global__ __launch_bounds__(256) void softmax_rows(
    float* __restrict__ attn, const int* __restrict__ mask)
{
    long long r = blockIdx.x;
    int q = (int)(r % SS);
    int b = (int)(r / ((long long)HH * SS));
    float* row = attn + r * (long long)SS;
    const int* mrow = mask + ((long long)b * SS + q) * SS;

    int tid = threadIdx.x;
    float4 vals[2];
    float mx = -CUDART_INF_F;
    #pragma unroll
    for (int i = 0; i < 2; i++) {
        int c = (tid + i * 256) * 4;
        float4 v = *(const float4*)&row[c];
        int4 mv = *(const int4*)&mrow[c];
        if (mv.x == 0) v.x = -1e9f;
        if (mv.y == 0) v.y = -1e9f;
        if (mv.z == 0) v.z = -1e9f;
        if (mv.w == 0) v.w = -1e9f;
        vals[i] = v;
        mx = fmaxf(mx, fmaxf(fmaxf(v.x, v.y), fmaxf(v.z, v.w)));
    }

    __shared__ float red[32];
    #pragma unroll
    for (int o = 16; o > 0; o >>= 1)
        mx = fmaxf(mx, __shfl_xor_sync(0xFFFFFFFF, mx, o));
    if ((tid & 31) == 0) red[tid >> 5] = mx;
    __syncthreads();
    if (tid < 32) {
        float v = (tid < 8) ? red[tid] : -CUDART_INF_F;
        #pragma unroll
        for (int o = 4; o > 0; o >>= 1)
            v = fmaxf(v, __shfl_xor_sync(0xFFFFFFFF, v, o));
        if (tid == 0) red[0] = v;
    }
    __syncthreads();
    mx = red[0];
    __syncthreads();

    float sum = 0.f;
    #pragma unroll
    for (int i = 0; i < 2; i++) {
        vals[i].x = __expf(vals[i].x - mx);
        vals[i].y = __expf(vals[i].y - mx);
        vals[i].z = __expf(vals[i].z - mx);
        vals[i].w = __expf(vals[i].w - mx);
        sum += vals[i].x + vals[i].y + vals[i].z + vals[i].w;
    }
    #pragma unroll
    for (int o = 16; o > 0; o >>= 1)
        sum += __shfl_xor_sync(0xFFFFFFFF, sum, o);
    if ((tid & 31) == 0) red[tid >> 5] = sum;
    __syncthreads();
    if (tid < 32) {
        float v = (tid < 8) ? red[tid] : 0.f;
        #pragma unroll
        for (int o = 4; o > 0; o >>= 1)
            v += __shfl_xor_sync(0xFFFFFFFF, v, o);
        if (tid == 0) red[0] = v;
    }
    __syncthreads();
    float inv = 1.f / red[0];

    #pragma unroll
    for (int i = 0; i < 2; i++) {
        int c = (tid + i * 256) * 4;
        float4 v = vals[i];
        v.x *= inv; v.y *= inv; v.z *= inv; v.w *= inv;
        *(float4*)&row[c] = v;
    }
}

// ---------------- launch ----------------
extern "C" void kernel_launch(void* const* d_in, const int* in_sizes, int n_in,
                              void* d_out, int out_size)
{
    const float* x    = (const float*)d_in[0];
    const int*   mask = (const int*)  d_in[1];
    const float* wq_w = (const float*)d_in[2];
    const float* wq_b = (const float*)d_in[3];
    const float* wk_w = (const float*)d_in[4];
    const float* wk_b = (const float*)d_in[5];
    const float* wv_w = (const float*)d_in[6];
    const float* wv_b = (const float*)d_in[7];
    const float* wo_w = (const float*)d_in[8];
    const float* wo_b = (const float*)d_in[9];

    float* out = (float*)d_out;

    const long long OUT_ELEMS  = (long long)BB * SS * DD;
    const long long ATTN_ELEMS = (long long)BB * HH * SS * SS;

    float *xt, *w, *bqk, *qk, *vt, *ctx, *attn;
    cudaGetSymbolAddress((void**)&xt,  g_xt);
    cudaGetSymbolAddress((void**)&w,   g_w);
    cudaGetSymbolAddress((void**)&bqk, g_bqk);
    cudaGetSymbolAddress((void**)&qk,  g_qk);
    cudaGetSymbolAddress((void**)&vt,  g_vt);
    cudaGetSymbolAddress((void**)&ctx, g_ctx);
    if ((long long)out_size >= OUT_ELEMS + ATTN_ELEMS) {
        attn = out + OUT_ELEMS;
    } else {
        cudaGetSymbolAddress((void**)&attn, g_attn);
    }

    const int M = BB * SS;           // 4096
    const int WELE = DD * DD;        // per-weight elems

    // 0) pre-round x and weights to tf32; pack q/k biases
    conv_tf32<<<(M * DD / 4 + 255) / 256, 256>>>((const float4*)x, (float4*)xt, M * DD / 4);
    conv_tf32<<<(WELE / 4 + 255) / 256, 256>>>((const float4*)wq_w, (float4*)(w + 0 * WELE), WELE / 4);
    conv_tf32<<<(WELE / 4 + 255) / 256, 256>>>((const float4*)wk_w, (float4*)(w + 1 * WELE), WELE / 4);
    conv_tf32<<<(WELE / 4 + 255) / 256, 256>>>((const float4*)wv_w, (float4*)(w + 2 * WELE), WELE / 4);
    conv_tf32<<<(WELE / 4 + 255) / 256, 256>>>((const float4*)wo_w, (float4*)(w + 3 * WELE), WELE / 4);
    pack_bias2<<<(DD + 255) / 256, 256>>>(wq_b, wk_b, bqk);

    // 1) Q and K projections in one launch (z=0:Q, z=1:K), rounded outputs
    {
        dim3 grid(DD / 128, M / 128, 2);
        gemm_cp<128, 128, 32, 64, 32, false, true, false><<<grid, 256>>>(
            xt, w, bqk, qk, DD,
            DD, DD, DD,
            0, 0,
            (long long)WELE, 0,
            (long long)M * DD, 0,
            DD, 1, 1.0f);
    }
    // 1b) V projection, transposed + rounded store into g_vt
    {
        dim3 grid(DD / 128, M / 128, 1);
        gemm_cp<128, 128, 32, 64, 32, false, true, true><<<grid, 256>>>(
            xt, w + 2 * WELE, wv_b, vt, DD,
            DD, DD, 0,
            0, 0, 0, 0, 0, 0, 0, 1, 1.0f);
    }

    // 2) scores[b,h] = SCALE * Q_h @ K_h^T  (into attn buffer, fp32)
    {
        dim3 grid(SS / 128, SS / 128, BB * HH);
        gemm_cp<128, 128, 32, 64, 32, false, false, false><<<grid, 256>>>(
            qk, qk + (long long)M * DD, nullptr, attn, DHH,
            DD, DD, SS,
            (long long)SS * DD, DHH,
            (long long)SS * DD, DHH,
            (long long)HH * SS * SS, (long long)SS * SS,
            0, HH, SCALE);
    }

    // 3) softmax rows in place (attn stays fp32 — exported)
    softmax_rows<<<(unsigned)((long long)BB * HH * SS), 256>>>(attn, mask);

    // 4) ctx = attn @ V  (A=attn rounded at load; B=vt k-contiguous)
    {
        dim3 grid(DHH / 64, SS / 128, BB * HH);
        gemm_cp<128, 64, 32, 32, 32, true, true, false><<<grid, 256>>>(
            attn, vt, nullptr, ctx, SS,
            SS, SS, DD,
            (long long)HH * SS * SS, (long long)SS * SS,
            (long long)DD * SS, (long long)DHH * SS,
            (long long)SS * DD, DHH,
            0, HH, 1.0f);
    }

    // 5) out = ctx @ wo^T + wo_b
    {
        dim3 grid(DD / 128, M / 128, 1);
        gemm_cp<128, 128, 32, 64, 32, false, false, false><<<grid, 256>>>(
            ctx, w + 3 * WELE, wo_b, out, DD,
            DD, DD, DD,
            0, 0, 0, 0, 0, 0, 0, 1, 1.0f);
    }
}